// round 8
// baseline (speedup 1.0000x reference)
#include <cuda_runtime.h>
#include <cuda_fp16.h>
#include <cstdint>

#define BB 16
#define SS 2048
#define HH 1024
#define DD 64
#define RR 2048
#define M_TOTAL (BB*SS)          // 32768 rows
#define NN 128                   // output cols (q | k)

#define BM 128
#define BN 128
#define BK 64
#define BKP 72                   // padded row length in fp16 (144B rows)
#define NKT (HH/BK)              // 16 chunks

// dynamic SMEM: per buffer [A16 | WH], each tile 128*72*2 = 18432 B
#define TILE_B   (128*BKP*2)
#define BUF_B    (2*TILE_B)      // 36864
#define SMEM_DYN (2*BUF_B)       // 73728

// Scratch: Q/K in fp16
__device__ __half g_Q[M_TOTAL * DD];
__device__ __half g_K[M_TOTAL * DD];
__device__ __half g_Wt_h[NN * HH];   // W^T fp16, [128][1024] K-major

// ---------------- helpers ----------------
__device__ __forceinline__ uint32_t smem_u32(const void* p) {
    uint32_t a;
    asm("{ .reg .u64 t; cvta.to.shared.u64 t, %1; cvt.u32.u64 %0, t; }"
        : "=r"(a) : "l"(p));
    return a;
}
// pack f16(lo),f16(hi): first PTX source lands in HIGH half
__device__ __forceinline__ uint32_t f2h2(float lo, float hi) {
    uint32_t r;
    asm("cvt.rn.f16x2.f32 %0, %1, %2;" : "=r"(r) : "f"(hi), "f"(lo));
    return r;
}
__device__ __forceinline__ void sts64(uint32_t addr, uint32_t a, uint32_t b) {
    asm volatile("st.shared.v2.b32 [%0], {%1,%2};" :: "r"(addr), "r"(a), "r"(b) : "memory");
}
__device__ __forceinline__ void cp16(uint32_t daddr, const void* src) {
    asm volatile("cp.async.cg.shared.global [%0], [%1], 16;"
                 :: "r"(daddr), "l"(src) : "memory");
}
__device__ __forceinline__ void cp_commit() {
    asm volatile("cp.async.commit_group;" ::: "memory");
}
__device__ __forceinline__ void cp_wait0() {
    asm volatile("cp.async.wait_group 0;" ::: "memory");
}
__device__ __forceinline__ void ldsm4(uint32_t addr, uint32_t& r0, uint32_t& r1,
                                      uint32_t& r2, uint32_t& r3) {
    asm volatile("ldmatrix.sync.aligned.m8n8.x4.shared.b16 {%0,%1,%2,%3}, [%4];"
                 : "=r"(r0), "=r"(r1), "=r"(r2), "=r"(r3) : "r"(addr));
}
// fp16-accumulate MMA: C/D are 2 packed f16x2 regs
__device__ __forceinline__ void mma16816h(uint32_t* c, uint32_t a0, uint32_t a1,
                                          uint32_t a2, uint32_t a3,
                                          uint32_t b0, uint32_t b1) {
    asm volatile(
        "mma.sync.aligned.m16n8k16.row.col.f16.f16.f16.f16 "
        "{%0,%1}, {%2,%3,%4,%5}, {%6,%7}, {%0,%1};"
        : "+r"(c[0]), "+r"(c[1])
        : "r"(a0), "r"(a1), "r"(a2), "r"(a3), "r"(b0), "r"(b1));
}

// ---------------------------------------------------------------------------
// Prep: W [1024][128] fp32 -> Wt_h [128][1024] fp16, tiled transpose
// ---------------------------------------------------------------------------
__global__ __launch_bounds__(256) void prep_w_kernel(const float* __restrict__ W) {
    __shared__ float t[32][33];
    const int k0 = blockIdx.x * 32;       // 32 tiles
    const int n0 = blockIdx.y * 32;       // 4 tiles
    const int r = threadIdx.x >> 5, c = threadIdx.x & 31;
#pragma unroll
    for (int i = 0; i < 4; ++i)
        t[r + 8 * i][c] = W[(size_t)(k0 + r + 8 * i) * NN + n0 + c];
    __syncthreads();
#pragma unroll
    for (int i = 0; i < 4; ++i) {
        const int n = n0 + r + 8 * i, k = k0 + c;
        g_Wt_h[(size_t)n * HH + k] = __float2half_rn(t[c][r + 8 * i]);
    }
}

// ---------------------------------------------------------------------------
// GEMM via mma.sync fp16 in/out/acc, double-buffered, BK=64.
// CTA: M=128, N=128, K=1024. 8 warps (2x4), warp tile 64x32. fp16 Q/K out.
// ---------------------------------------------------------------------------
__global__ __launch_bounds__(256, 2) void gemm_mma_kernel(
    const float* __restrict__ A,       // [M_TOTAL, 1024]
    const float* __restrict__ bias,    // [128]
    const int*   __restrict__ pos_ids  // [M_TOTAL]
) {
    extern __shared__ char dsm[];
    const uint32_t sbase = smem_u32(dsm);

    const int tid  = threadIdx.x;
    const int lane = tid & 31;
    const int warp = tid >> 5;
    const int wm   = warp >> 2;       // 0..1
    const int wn   = warp & 3;        // 0..3
    const int blockM = blockIdx.x * BM;

    uint32_t acc[4][4][2];
#pragma unroll
    for (int m = 0; m < 4; ++m)
#pragma unroll
        for (int n = 0; n < 4; ++n) { acc[m][n][0] = 0u; acc[m][n][1] = 0u; }

    // ---- load mappings ----
    const int arow  = tid >> 1;       // 0..127
    const int ahalf = tid & 1;        // 32-float half of the 64-wide chunk
    const int bn    = tid & 127;      // B row (n)
    const int bp    = tid >> 7;       // 0..1: 64B half of the 128B row chunk

    // ldmatrix per-thread address pieces
    const int a_lr   = lane & 7;
    const int a_tile = lane >> 3;
    const uint32_t a_addr_base =
        (uint32_t)(((wm * 64 + (a_tile & 1) * 8 + a_lr) * BKP + (a_tile >> 1) * 8) * 2);
    const uint32_t b_addr_base =
        (uint32_t)(((wn * 32 + (a_tile >> 1) * 8 + a_lr) * BKP + (a_tile & 1) * 8) * 2);

    float4 aldg[8];
    const float4* Ag = reinterpret_cast<const float4*>(A);

    // B cp.async source/dest pieces
    const __half* bsrc_h = &g_Wt_h[(size_t)bn * HH + bp * 32];
    const uint32_t bdst_off = (uint32_t)(bn * (BKP * 2) + bp * 64);

    // ---- prologue: chunk 0 into buf 0 ----
    {
        const uint32_t buf = sbase;
#pragma unroll
        for (int j = 0; j < 4; ++j)
            cp16(buf + TILE_B + bdst_off + j * 16, bsrc_h + j * 8);
        cp_commit();
#pragma unroll
        for (int i = 0; i < 8; ++i)
            aldg[i] = Ag[((size_t)(blockM + arow) * HH) / 4 + ahalf * 8 + i];
#pragma unroll
        for (int i = 0; i < 8; ++i) {
            uint32_t p0 = f2h2(aldg[i].x, aldg[i].y);
            uint32_t p1 = f2h2(aldg[i].z, aldg[i].w);
            sts64(buf + (uint32_t)((arow * BKP + ahalf * 32 + i * 4) * 2), p0, p1);
        }
        cp_wait0();
        __syncthreads();
    }

    for (int kt = 0; kt < NKT; ++kt) {
        const uint32_t cur = sbase + (kt & 1) * BUF_B;
        const uint32_t nxt = sbase + ((kt + 1) & 1) * BUF_B;
        const bool more = (kt + 1 < NKT);

        if (more) {
            const int k0 = (kt + 1) * BK;
#pragma unroll
            for (int j = 0; j < 4; ++j)
                cp16(nxt + TILE_B + bdst_off + j * 16, bsrc_h + k0 + j * 8);
            cp_commit();
#pragma unroll
            for (int i = 0; i < 8; ++i)
                aldg[i] = Ag[((size_t)(blockM + arow) * HH + k0) / 4 + ahalf * 8 + i];
        }

        // ---- compute on cur: 4 k16 steps ----
        const uint32_t sA = cur, sBH = cur + TILE_B;
#pragma unroll
        for (int kk = 0; kk < BK; kk += 16) {
            uint32_t bh[2][4];
#pragma unroll
            for (int n2 = 0; n2 < 2; ++n2) {
                uint32_t boff = b_addr_base + (uint32_t)((n2 * 16 * BKP + kk) * 2);
                ldsm4(sBH + boff, bh[n2][0], bh[n2][1], bh[n2][2], bh[n2][3]);
            }
#pragma unroll
            for (int m = 0; m < 4; ++m) {
                uint32_t aoff = a_addr_base + (uint32_t)((m * 16 * BKP + kk) * 2);
                uint32_t a0, a1, a2, a3;
                ldsm4(sA + aoff, a0, a1, a2, a3);
#pragma unroll
                for (int n = 0; n < 4; ++n)
                    mma16816h(acc[m][n], a0, a1, a2, a3,
                              bh[n >> 1][(n & 1) * 2], bh[n >> 1][(n & 1) * 2 + 1]);
            }
        }

        if (more) {
#pragma unroll
            for (int i = 0; i < 8; ++i) {
                uint32_t p0 = f2h2(aldg[i].x, aldg[i].y);
                uint32_t p1 = f2h2(aldg[i].z, aldg[i].w);
                sts64(nxt + (uint32_t)((arow * BKP + ahalf * 32 + i * 4) * 2), p0, p1);
            }
            cp_wait0();
        }
        __syncthreads();
    }

    // ---- epilogue: bias + RoPE + fp16 split store ----
    const float LN1E4_OVER_32 = 0.28782313662425574f;   // ln(10000)/32
#pragma unroll
    for (int n = 0; n < 4; ++n) {
        const int col  = wn * 32 + n * 8 + (lane & 3) * 2;   // even
        const bool is_q = (col < DD);
        const int dloc  = col & (DD - 1);
        const float fr  = __expf(-(float)(dloc >> 1) * LN1E4_OVER_32);
        const float b0 = bias[col], b1 = bias[col + 1];
        __half* dst = is_q ? g_Q : g_K;
#pragma unroll
        for (int m = 0; m < 4; ++m) {
            const int ra = blockM + wm * 64 + m * 16 + (lane >> 2);
#pragma unroll
            for (int h = 0; h < 2; ++h) {
                const int r = ra + h * 8;
                const float pos = (float)__ldg(&pos_ids[r]);
                float s, c;
                sincosf(pos * fr, &s, &c);
                float2 xv = __half22float2(
                    *reinterpret_cast<const __half2*>(&acc[m][n][h]));
                const float x0 = xv.x + b0;
                const float x1 = xv.y + b1;
                __half2 y = __floats2half2_rn(x0 * c - x1 * s, x1 * c + x0 * s);
                *reinterpret_cast<__half2*>(&dst[(size_t)r * DD + dloc]) = y;
            }
        }
    }
}

// ---------------------------------------------------------------------------
// Relation gather + dot + mask. Two relations per warp (16 lanes each).
// ---------------------------------------------------------------------------
__global__ __launch_bounds__(256) void relation_kernel(
    const int*   __restrict__ rel_idx,  // [B*R, 4]
    const float* __restrict__ mask,     // [B*R]
    float*       __restrict__ out       // [B*R]
) {
    const int warp = (blockIdx.x * blockDim.x + threadIdx.x) >> 5;
    const int lane = threadIdx.x & 31;
    const int seg  = lane >> 4;          // 0 or 1: relation within warp
    const int sl   = lane & 15;
    const int rel  = warp * 2 + seg;
    if (rel >= BB * RR) return;

    const int b    = rel / RR;
    const int4 idx = reinterpret_cast<const int4*>(rel_idx)[rel];
    const int base = b * SS;

    // lanes 0-7 of the 16: q0.k2; lanes 8-15: q1.k3 (each lane 16B = 8 halves)
    const int half2sel = sl >> 3;        // 0/1
    const int hsl      = sl & 7;
    const int qrow = base + (half2sel ? idx.y : idx.x);
    const int krow = base + (half2sel ? idx.w : idx.z);
    uint4 qa = reinterpret_cast<const uint4*>(&g_Q[(size_t)qrow * DD])[hsl];
    uint4 ka = reinterpret_cast<const uint4*>(&g_K[(size_t)krow * DD])[hsl];

    float sum = 0.0f;
    {
        const __half2* qh = reinterpret_cast<const __half2*>(&qa);
        const __half2* kh = reinterpret_cast<const __half2*>(&ka);
#pragma unroll
        for (int j = 0; j < 4; ++j) {
            float2 q = __half22float2(qh[j]);
            float2 k = __half22float2(kh[j]);
            sum += q.x * k.x + q.y * k.y;
        }
    }
#pragma unroll
    for (int off = 8; off > 0; off >>= 1)
        sum += __shfl_xor_sync(0xffffffffu, sum, off);

    if (sl == 0) {
        const float m = mask[rel];
        out[rel] = (sum + (1.0f - m) * -1e12f) * 0.125f;  // 1/sqrt(64)
    }
}

extern "C" void kernel_launch(void* const* d_in, const int* in_sizes, int n_in,
                              void* d_out, int out_size) {
    const float* lhs  = (const float*)d_in[0];   // [B,S,H]
    const float* W    = (const float*)d_in[1];   // [H,128]
    const float* bias = (const float*)d_in[2];   // [128]
    const int*   pos  = (const int*)d_in[3];     // [B,S]
    const int*   ridx = (const int*)d_in[4];     // [B,R,4]
    const float* lm   = (const float*)d_in[5];   // [B,R]
    float* out = (float*)d_out;                  // [B,R]

    static bool attr_set = false;
    if (!attr_set) {
        cudaFuncSetAttribute(gemm_mma_kernel,
                             cudaFuncAttributeMaxDynamicSharedMemorySize, SMEM_DYN);
        attr_set = true;
    }
    prep_w_kernel<<<dim3(32, 4), 256>>>(W);
    gemm_mma_kernel<<<M_TOTAL / BM, 256, SMEM_DYN>>>(lhs, bias, pos);
    relation_kernel<<<(BB * RR / 2 + 7) / 8, 256>>>(ridx, lm, out);
}

// round 9
// speedup vs baseline: 1.5517x; 1.5517x over previous
#include <cuda_runtime.h>
#include <cuda_fp16.h>
#include <cstdint>

#define BB 16
#define SS 2048
#define HH 1024
#define DD 64
#define RR 2048
#define M_TOTAL (BB*SS)          // 32768 rows
#define NN 128                   // output cols (q | k)

#define BM 128
#define BN 128
#define BK 32
#define BKP 40                   // padded row length in fp16 (80B rows)
#define NKT (HH/BK)              // 32 k-chunks

// dynamic SMEM: per buffer [A16 | WH], each tile 128*40*2 = 10240 B
#define TILE_B   (128*BKP*2)
#define BUF_B    (2*TILE_B)      // 20480
#define SMEM_DYN (2*BUF_B)       // 40960

// Scratch: Q/K in fp16
__device__ __half g_Q[M_TOTAL * DD];
__device__ __half g_K[M_TOTAL * DD];
__device__ __half g_Wt_h[NN * HH];   // W^T fp16, [128][1024] K-major

// ---------------- helpers ----------------
__device__ __forceinline__ uint32_t smem_u32(const void* p) {
    uint32_t a;
    asm("{ .reg .u64 t; cvta.to.shared.u64 t, %1; cvt.u32.u64 %0, t; }"
        : "=r"(a) : "l"(p));
    return a;
}
// pack f16(lo),f16(hi): first PTX source lands in HIGH half
__device__ __forceinline__ uint32_t f2h2(float lo, float hi) {
    uint32_t r;
    asm("cvt.rn.f16x2.f32 %0, %1, %2;" : "=r"(r) : "f"(hi), "f"(lo));
    return r;
}
__device__ __forceinline__ void sts64(uint32_t addr, uint32_t a, uint32_t b) {
    asm volatile("st.shared.v2.b32 [%0], {%1,%2};" :: "r"(addr), "r"(a), "r"(b) : "memory");
}
__device__ __forceinline__ void cp16(uint32_t daddr, const void* src) {
    asm volatile("cp.async.cg.shared.global [%0], [%1], 16;"
                 :: "r"(daddr), "l"(src) : "memory");
}
__device__ __forceinline__ void cp_commit() {
    asm volatile("cp.async.commit_group;" ::: "memory");
}
__device__ __forceinline__ void cp_wait0() {
    asm volatile("cp.async.wait_group 0;" ::: "memory");
}
__device__ __forceinline__ void ldsm4(uint32_t addr, uint32_t& r0, uint32_t& r1,
                                      uint32_t& r2, uint32_t& r3) {
    asm volatile("ldmatrix.sync.aligned.m8n8.x4.shared.b16 {%0,%1,%2,%3}, [%4];"
                 : "=r"(r0), "=r"(r1), "=r"(r2), "=r"(r3) : "r"(addr));
}
__device__ __forceinline__ void mma16816(float* c, uint32_t a0, uint32_t a1,
                                         uint32_t a2, uint32_t a3,
                                         uint32_t b0, uint32_t b1) {
    asm volatile(
        "mma.sync.aligned.m16n8k16.row.col.f32.f16.f16.f32 "
        "{%0,%1,%2,%3}, {%4,%5,%6,%7}, {%8,%9}, {%0,%1,%2,%3};"
        : "+f"(c[0]), "+f"(c[1]), "+f"(c[2]), "+f"(c[3])
        : "r"(a0), "r"(a1), "r"(a2), "r"(a3), "r"(b0), "r"(b1));
}

// ---------------------------------------------------------------------------
// Prep: W [1024][128] fp32 -> Wt_h [128][1024] fp16, tiled transpose
// ---------------------------------------------------------------------------
__global__ __launch_bounds__(256) void prep_w_kernel(const float* __restrict__ W) {
    __shared__ float t[32][33];
    const int k0 = blockIdx.x * 32;       // 32 tiles
    const int n0 = blockIdx.y * 32;       // 4 tiles
    const int r = threadIdx.x >> 5, c = threadIdx.x & 31;
#pragma unroll
    for (int i = 0; i < 4; ++i)
        t[r + 8 * i][c] = W[(size_t)(k0 + r + 8 * i) * NN + n0 + c];
    __syncthreads();
#pragma unroll
    for (int i = 0; i < 4; ++i) {
        const int n = n0 + r + 8 * i, k = k0 + c;
        g_Wt_h[(size_t)n * HH + k] = __float2half_rn(t[c][r + 8 * i]);
    }
}

// ---------------------------------------------------------------------------
// GEMM via mma.sync fp16 in / f32 acc, double-buffered, produce-before-compute.
// CTA: M=128, N=128, K=1024. 8 warps (2x4), warp tile 64x32. fp16 Q/K out.
// ---------------------------------------------------------------------------
__global__ __launch_bounds__(256, 2) void gemm_mma_kernel(
    const float* __restrict__ A,       // [M_TOTAL, 1024]
    const float* __restrict__ bias,    // [128]
    const int*   __restrict__ pos_ids  // [M_TOTAL]
) {
    extern __shared__ char dsm[];
    const uint32_t sbase = smem_u32(dsm);

    const int tid  = threadIdx.x;
    const int lane = tid & 31;
    const int warp = tid >> 5;
    const int wm   = warp >> 2;       // 0..1
    const int wn   = warp & 3;        // 0..3
    const int blockM = blockIdx.x * BM;

    float acc[4][4][4];
#pragma unroll
    for (int m = 0; m < 4; ++m)
#pragma unroll
        for (int n = 0; n < 4; ++n)
#pragma unroll
            for (int f = 0; f < 4; ++f) acc[m][n][f] = 0.0f;

    // ---- load mappings ----
    const int arow0 = tid >> 3;       // 0..31 (rows arow0 + 32*i)
    const int af    = tid & 7;        // float4 index within 32-float k-chunk
    const int bn    = tid & 127;      // B row (n)
    const int bp    = tid >> 7;       // 0..1: 32B half of the 64B row chunk

    // ldmatrix per-thread address pieces
    const int a_lr   = lane & 7;
    const int a_tile = lane >> 3;
    const uint32_t a_addr_base =
        (uint32_t)(((wm * 64 + (a_tile & 1) * 8 + a_lr) * BKP + (a_tile >> 1) * 8) * 2);
    const uint32_t b_addr_base =
        (uint32_t)(((wn * 32 + (a_tile >> 1) * 8 + a_lr) * BKP + (a_tile & 1) * 8) * 2);

    float4 aldg[4];
    const float4* Ag = reinterpret_cast<const float4*>(A);

    // B cp.async source/dest pieces
    const __half* bsrc_h = &g_Wt_h[(size_t)bn * HH + bp * 16];
    const uint32_t bdst_off = (uint32_t)(bn * (BKP * 2) + bp * 32);

    // ---- prologue ----
    // invariant at loop iter kt: cur buffer holds chunk kt (A in smem, B waited),
    // aldg registers hold A of chunk kt+1.
    {
        const uint32_t buf = sbase;
        cp16(buf + TILE_B + bdst_off,      bsrc_h);
        cp16(buf + TILE_B + bdst_off + 16, bsrc_h + 8);
        cp_commit();
#pragma unroll
        for (int i = 0; i < 4; ++i)
            aldg[i] = Ag[((size_t)(blockM + arow0 + 32 * i) * HH) / 4 + af];
#pragma unroll
        for (int i = 0; i < 4; ++i) {
            uint32_t p0 = f2h2(aldg[i].x, aldg[i].y);
            uint32_t p1 = f2h2(aldg[i].z, aldg[i].w);
            uint32_t off = (uint32_t)((arow0 + 32 * i) * (BKP * 2) + af * 8);
            sts64(buf + off, p0, p1);
        }
#pragma unroll
        for (int i = 0; i < 4; ++i)
            aldg[i] = Ag[((size_t)(blockM + arow0 + 32 * i) * HH + BK) / 4 + af];
        cp_wait0();
        __syncthreads();
    }

    for (int kt = 0; kt < NKT; ++kt) {
        const uint32_t cur = sbase + (kt & 1) * BUF_B;
        const uint32_t nxt = sbase + ((kt + 1) & 1) * BUF_B;
        const bool more = (kt + 1 < NKT);

        // ---- produce chunk kt+1 into nxt (before compute) ----
        if (more) {
            const int kb = (kt + 1) * BK;
            cp16(nxt + TILE_B + bdst_off,      bsrc_h + kb);
            cp16(nxt + TILE_B + bdst_off + 16, bsrc_h + kb + 8);
            cp_commit();
#pragma unroll
            for (int i = 0; i < 4; ++i) {
                uint32_t p0 = f2h2(aldg[i].x, aldg[i].y);
                uint32_t p1 = f2h2(aldg[i].z, aldg[i].w);
                uint32_t off = (uint32_t)((arow0 + 32 * i) * (BKP * 2) + af * 8);
                sts64(nxt + off, p0, p1);
            }
            if (kt + 2 < NKT) {
                const int kn = (kt + 2) * BK;
#pragma unroll
                for (int i = 0; i < 4; ++i)
                    aldg[i] = Ag[((size_t)(blockM + arow0 + 32 * i) * HH + kn) / 4 + af];
            }
        }

        // ---- compute on cur: 2 k16 steps ----
        const uint32_t sA = cur, sBH = cur + TILE_B;
#pragma unroll
        for (int kk = 0; kk < BK; kk += 16) {
            uint32_t bh[2][4];
#pragma unroll
            for (int n2 = 0; n2 < 2; ++n2) {
                uint32_t boff = b_addr_base + (uint32_t)((n2 * 16 * BKP + kk) * 2);
                ldsm4(sBH + boff, bh[n2][0], bh[n2][1], bh[n2][2], bh[n2][3]);
            }
#pragma unroll
            for (int m = 0; m < 4; ++m) {
                uint32_t aoff = a_addr_base + (uint32_t)((m * 16 * BKP + kk) * 2);
                uint32_t a0, a1, a2, a3;
                ldsm4(sA + aoff, a0, a1, a2, a3);
#pragma unroll
                for (int n = 0; n < 4; ++n)
                    mma16816(acc[m][n], a0, a1, a2, a3,
                             bh[n >> 1][(n & 1) * 2], bh[n >> 1][(n & 1) * 2 + 1]);
            }
        }

        if (more) cp_wait0();
        __syncthreads();
    }

    // ---- epilogue: bias + RoPE + fp16 split store ----
    const float LN1E4_OVER_32 = 0.28782313662425574f;   // ln(10000)/32
#pragma unroll
    for (int n = 0; n < 4; ++n) {
        const int col  = wn * 32 + n * 8 + (lane & 3) * 2;   // even
        const bool is_q = (col < DD);
        const int dloc  = col & (DD - 1);
        const float fr  = __expf(-(float)(dloc >> 1) * LN1E4_OVER_32);
        const float b0 = bias[col], b1 = bias[col + 1];
        __half* dst = is_q ? g_Q : g_K;
#pragma unroll
        for (int m = 0; m < 4; ++m) {
            const int ra = blockM + wm * 64 + m * 16 + (lane >> 2);
#pragma unroll
            for (int h = 0; h < 2; ++h) {
                const int r = ra + h * 8;
                const float pos = (float)__ldg(&pos_ids[r]);
                float s, c;
                __sincosf(pos * fr, &s, &c);
                const float x0 = acc[m][n][2 * h]     + b0;
                const float x1 = acc[m][n][2 * h + 1] + b1;
                __half2 y = __floats2half2_rn(x0 * c - x1 * s, x1 * c + x0 * s);
                *reinterpret_cast<__half2*>(&dst[(size_t)r * DD + dloc]) = y;
            }
        }
    }
}

// ---------------------------------------------------------------------------
// Relation gather + dot + mask. Two relations per warp (16 lanes each).
// ---------------------------------------------------------------------------
__global__ __launch_bounds__(256) void relation_kernel(
    const int*   __restrict__ rel_idx,  // [B*R, 4]
    const float* __restrict__ mask,     // [B*R]
    float*       __restrict__ out       // [B*R]
) {
    const int warp = (blockIdx.x * blockDim.x + threadIdx.x) >> 5;
    const int lane = threadIdx.x & 31;
    const int seg  = lane >> 4;          // 0 or 1: relation within warp
    const int sl   = lane & 15;
    const int rel  = warp * 2 + seg;
    if (rel >= BB * RR) return;

    const int b    = rel / RR;
    const int4 idx = reinterpret_cast<const int4*>(rel_idx)[rel];
    const int base = b * SS;

    // lanes 0-7 of the 16: q0.k2; lanes 8-15: q1.k3 (each lane 16B = 8 halves)
    const int half2sel = sl >> 3;        // 0/1
    const int hsl      = sl & 7;
    const int qrow = base + (half2sel ? idx.y : idx.x);
    const int krow = base + (half2sel ? idx.w : idx.z);
    uint4 qa = reinterpret_cast<const uint4*>(&g_Q[(size_t)qrow * DD])[hsl];
    uint4 ka = reinterpret_cast<const uint4*>(&g_K[(size_t)krow * DD])[hsl];

    float sum = 0.0f;
    {
        const __half2* qh = reinterpret_cast<const __half2*>(&qa);
        const __half2* kh = reinterpret_cast<const __half2*>(&ka);
#pragma unroll
        for (int j = 0; j < 4; ++j) {
            float2 q = __half22float2(qh[j]);
            float2 k = __half22float2(kh[j]);
            sum += q.x * k.x + q.y * k.y;
        }
    }
#pragma unroll
    for (int off = 8; off > 0; off >>= 1)
        sum += __shfl_xor_sync(0xffffffffu, sum, off);

    if (sl == 0) {
        const float m = mask[rel];
        out[rel] = (sum + (1.0f - m) * -1e12f) * 0.125f;  // 1/sqrt(64)
    }
}

extern "C" void kernel_launch(void* const* d_in, const int* in_sizes, int n_in,
                              void* d_out, int out_size) {
    const float* lhs  = (const float*)d_in[0];   // [B,S,H]
    const float* W    = (const float*)d_in[1];   // [H,128]
    const float* bias = (const float*)d_in[2];   // [128]
    const int*   pos  = (const int*)d_in[3];     // [B,S]
    const int*   ridx = (const int*)d_in[4];     // [B,R,4]
    const float* lm   = (const float*)d_in[5];   // [B,R]
    float* out = (float*)d_out;                  // [B,R]

    static bool attr_set = false;
    if (!attr_set) {
        cudaFuncSetAttribute(gemm_mma_kernel,
                             cudaFuncAttributeMaxDynamicSharedMemorySize, SMEM_DYN);
        attr_set = true;
    }
    prep_w_kernel<<<dim3(32, 4), 256>>>(W);
    gemm_mma_kernel<<<M_TOTAL / BM, 256, SMEM_DYN>>>(lhs, bias, pos);
    relation_kernel<<<(BB * RR / 2 + 7) / 8, 256>>>(ridx, lm, out);
}